// round 15
// baseline (speedup 1.0000x reference)
#include <cuda_runtime.h>
#include <cuda_fp16.h>
#include <cstdint>

#define BB 1024
#define TT 256
#define HH 256
#define OUTD 9
#define PL 16
#define INPAD 272   // 9 + 256 = 265, padded to 272

typedef unsigned long long u64;

// ---------------- device scratch ----------------
__device__ __align__(16) float g_reprs[BB * TT * 3];
__device__ __align__(16) __half g_enc16[(size_t)BB * TT * HH];
__device__ __align__(16) __half g_eproj16[(size_t)BB * TT * HH];
__device__ __align__(16) float g_h1[BB * HH];         // final encoder h (fp32)
__device__ __align__(16) float g_hd[2][BB * HH];
__device__ __align__(16) float g_inp[BB * INPAD];
__device__ __align__(16) __half g_wtdT16[HH * HH];    // transposed Wt_dec fp16
__device__ __align__(16) __half g_wte16[HH * HH];
__device__ __align__(16) __half g_wgru16[8 * 128 * 528];  // [hg][128 rows][528 k]

// ---------------- math helpers ----------------
__device__ __forceinline__ float ex2f(float x) {
    float r; asm("ex2.approx.f32 %0, %1;" : "=f"(r) : "f"(x)); return r;
}
__device__ __forceinline__ float frcp(float x) {
    float r; asm("rcp.approx.f32 %0, %1;" : "=f"(r) : "f"(x)); return r;
}
__device__ __forceinline__ float sigf(float x) {
    return frcp(1.0f + ex2f(-1.4426950408889634f * x));
}
__device__ __forceinline__ float tanhf_fast(float x) {
    float ax = fabsf(x);
    float e = ex2f(-2.8853900817779268f * ax);
    float r = (1.0f - e) * frcp(1.0f + e);
    return copysignf(r, x);
}
__device__ __forceinline__ float tanh_apx(float x) {
    float r; asm("tanh.approx.f32 %0, %1;" : "=f"(r) : "f"(x)); return r;
}
__device__ __forceinline__ float warp_sum(float v) {
#pragma unroll
    for (int o = 16; o > 0; o >>= 1) v += __shfl_xor_sync(0xffffffffu, v, o);
    return v;
}
__device__ __forceinline__ uint32_t smem_u32(const void* p) {
    uint32_t a;
    asm("{ .reg .u64 t; cvta.to.shared.u64 t, %1; cvt.u32.u64 %0, t; }"
        : "=r"(a) : "l"(p));
    return a;
}
__device__ __forceinline__ uint32_t mapa_rank(uint32_t addr, uint32_t r) {
    uint32_t d;
    asm("mapa.shared::cluster.u32 %0, %1, %2;" : "=r"(d) : "r"(addr), "r"(r));
    return d;
}
__device__ __forceinline__ void st_cluster_v4(uint32_t addr, uint4 v) {
    asm volatile("st.shared::cluster.v4.b32 [%0], {%1,%2,%3,%4};"
        :: "r"(addr), "r"(v.x), "r"(v.y), "r"(v.z), "r"(v.w) : "memory");
}
__device__ __forceinline__ uint32_t cluster_rank() {
    uint32_t r; asm("mov.u32 %0, %%cluster_ctarank;" : "=r"(r)); return r;
}
__device__ __forceinline__ void cluster_sync() {
    asm volatile("barrier.cluster.arrive.aligned;" ::: "memory");
    asm volatile("barrier.cluster.wait.aligned;" ::: "memory");
}
__device__ __forceinline__ void ldm4(uint32_t* r, uint32_t addr) {
    asm volatile("ldmatrix.sync.aligned.m8n8.x4.shared.b16 {%0,%1,%2,%3}, [%4];"
        : "=r"(r[0]), "=r"(r[1]), "=r"(r[2]), "=r"(r[3]) : "r"(addr));
}
__device__ __forceinline__ void mma16816(float* c,
        uint32_t a0, uint32_t a1, uint32_t a2, uint32_t a3,
        uint32_t b0, uint32_t b1) {
    asm volatile(
        "mma.sync.aligned.m16n8k16.row.col.f32.f16.f16.f32 "
        "{%0,%1,%2,%3}, {%4,%5,%6,%7}, {%8,%9}, {%0,%1,%2,%3};"
        : "+f"(c[0]), "+f"(c[1]), "+f"(c[2]), "+f"(c[3])
        : "r"(a0), "r"(a1), "r"(a2), "r"(a3), "r"(b0), "r"(b1));
}

// ---------------- init ----------------
__global__ void init_a_kernel(const float* __restrict__ x) {
    int idx = blockIdx.x * blockDim.x + threadIdx.x;
    int stride = gridDim.x * blockDim.x;
    for (int i = idx; i < BB * INPAD; i += stride) {
        int b = i / INPAD, c = i - b * INPAD;
        g_inp[i] = (c < OUTD) ? x[((size_t)b * TT + (TT - 1)) * OUTD + c] : 0.0f;
    }
}
// merged weight prep (Wt halves + decoder GRU pack)
__global__ void init_w_kernel(const float* __restrict__ Wt,
                              const float* __restrict__ dWih,
                              const float* __restrict__ dWhh) {
    int idx = blockIdx.x * blockDim.x + threadIdx.x;
    int stride = gridDim.x * blockDim.x;
    for (int i = idx; i < HH * HH; i += stride) {
        int k = i >> 8, n = i & 255;
        g_wtdT16[i] = __float2half_rn(Wt[n * (2 * HH) + k]);
        int g = i >> 8, c = i & 255;
        g_wte16[i] = __float2half_rn(Wt[g * (2 * HH) + HH + c]);
    }
    const int TOT = 8 * 128 * 528;
    for (int i = idx; i < TOT; i += stride) {
        int hg = i / (128 * 528);
        int rem = i - hg * (128 * 528);
        int row = rem / 528;
        int k = rem - row * 528;
        int cls = row >> 5, hh = row & 31;
        int gr = hg * 32 + hh;
        float v = 0.0f;
        if (cls == 0) {
            v = (k < 256) ? dWhh[(size_t)(0 * 256 + gr) * 256 + k]
                : ((k - 256 < 265) ? dWih[(size_t)(0 * 256 + gr) * 265 + (k - 256)] : 0.0f);
        } else if (cls == 1) {
            v = (k < 256) ? dWhh[(size_t)(1 * 256 + gr) * 256 + k]
                : ((k - 256 < 265) ? dWih[(size_t)(1 * 256 + gr) * 265 + (k - 256)] : 0.0f);
        } else if (cls == 2) {
            v = (k < 256) ? dWhh[(size_t)(2 * 256 + gr) * 256 + k] : 0.0f;
        } else {
            v = (k >= 256 && k - 256 < 265) ? dWih[(size_t)(2 * 256 + gr) * 265 + (k - 256)] : 0.0f;
        }
        g_wgru16[i] = __float2half_rn(v);
    }
}

// ---------------- stage 1: agent attention (tanh.approx) ----------------
__global__ __launch_bounds__(256) void agent_attn_kernel(
        const float* __restrict__ x, const float* __restrict__ Wa,
        const float* __restrict__ ba, const float* __restrict__ va) {
    __shared__ float Was[HH * 3];
    __shared__ float vas[HH];
    __shared__ float bas[HH];
    int tid = threadIdx.x;
    for (int i = tid; i < HH * 3; i += 256) Was[i] = Wa[i];
    vas[tid] = va[tid];
    bas[tid] = ba[tid];
    __syncthreads();

    int pair = blockIdx.x * 8 + (tid >> 5);
    int lane = tid & 31;
    const float* xp = &x[(size_t)pair * 9];
    float xv[9];
#pragma unroll
    for (int i = 0; i < 9; i++) xv[i] = xp[i];

    float sc[3];
#pragma unroll
    for (int a = 0; a < 3; a++) {
        float s = 0.0f;
        float x0 = xv[a * 3], x1 = xv[a * 3 + 1], x2 = xv[a * 3 + 2];
#pragma unroll
        for (int i = 0; i < 8; i++) {
            int h = lane + 32 * i;
            float e = tanh_apx(fmaf(x2, Was[h * 3 + 2],
                          fmaf(x1, Was[h * 3 + 1], x0 * Was[h * 3])) + bas[h]);
            s += e * vas[h];
        }
        sc[a] = warp_sum(s);
    }
    float m = fmaxf(sc[0], fmaxf(sc[1], sc[2]));
    float e0 = ex2f((sc[0] - m) * 1.4426950408889634f);
    float e1 = ex2f((sc[1] - m) * 1.4426950408889634f);
    float e2 = ex2f((sc[2] - m) * 1.4426950408889634f);
    float inv = frcp(e0 + e1 + e2);
    float a0 = e0 * inv, a1 = e1 * inv, a2 = e2 * inv;
    if (lane < 3) {
        g_reprs[pair * 3 + lane] =
            a0 * xv[lane] + a1 * xv[3 + lane] + a2 * xv[6 + lane];
    }
}

// ---------------- stage 2: cluster-DSMEM persistent encoder ----------------
// 128 CTAs = 16 clusters of 8. cluster = batch group (64 rows); rank = h-group.
// h exchanged by direct st.shared::cluster into peers' double-buffered A tiles.
#define ROWB 528
#define A0_OFF 0
#define A1_OFF (64 * ROWB)                    // 33792
#define BH_OFF (2 * 64 * ROWB)                // 67584
#define GH_OFF (BH_OFF + 96 * ROWB)           // 118272
#define X2_OFF (GH_OFF + 64 * 100 * 4)        // 143872
#define WI2_OFF (X2_OFF + 192 * 4)
#define BI2_OFF (WI2_OFF + 288 * 4)
#define BH2_OFF (BI2_OFF + 96 * 4)
#define ENC_SMEM (BH2_OFF + 96 * 4)

__global__ __launch_bounds__(256, 1) __cluster_dims__(8, 1, 1)
void enc_persistent(
        const float* __restrict__ Whh, const float* __restrict__ Wih,
        const float* __restrict__ bih, const float* __restrict__ bhh) {
    extern __shared__ __align__(16) char smraw[];
    uint32_t smem_base = smem_u32(smraw);
    float* ghs  = (float*)(smraw + GH_OFF);
    float* Xs   = (float*)(smraw + X2_OFF);
    float* wihs = (float*)(smraw + WI2_OFF);
    float* bihs = (float*)(smraw + BI2_OFF);
    float* bhhs = (float*)(smraw + BH2_OFF);

    int tid = threadIdx.x;
    int wid = tid >> 5, lane = tid & 31;
    int bg  = blockIdx.x >> 3;
    int bm0 = bg * 64;
    uint32_t rank = cluster_rank();
    int hb0 = (int)rank * 32;

    // zero BOTH A buffers (t=0 h = 0; padding stays 0)
    for (int i = tid; i < (2 * 64 * ROWB) / 16; i += 256)
        ((uint4*)smraw)[i] = make_uint4(0, 0, 0, 0);

    for (int i = tid; i < 96 * 128; i += 256) {
        int n = i >> 7, kp = i & 127;
        int g = n >> 5, hh = n & 31;
        float2 w = *(const float2*)&Whh[(size_t)(g * HH + hb0 + hh) * HH + kp * 2];
        *(__half2*)(smraw + BH_OFF + n * ROWB + kp * 4) = __floats2half2_rn(w.x, w.y);
    }
    for (int i = tid; i < 288; i += 256) {
        int g = i / 96, r = i % 96, hh = r / 3, f = r % 3;
        wihs[(g * 32 + hh) * 3 + f] = Wih[(size_t)(g * HH + hb0 + hh) * 3 + f];
    }
    if (tid < 96) {
        int g = tid >> 5, hh = tid & 31;
        bihs[g * 32 + hh] = bih[g * HH + hb0 + hh];
        bhhs[g * 32 + hh] = bhh[g * HH + hb0 + hh];
    }
    __syncthreads();
    cluster_sync();   // A buffers zeroed everywhere before anyone writes/reads

    int mw = wid >> 1, nw = wid & 1;
    uint32_t a_off = (uint32_t)(((lane & 7) + ((lane >> 3) & 1) * 8) * ROWB
                                + ((lane >> 4) & 1) * 16);
    uint32_t b_off = (uint32_t)(((lane & 7) + ((lane >> 4) & 1) * 8) * ROWB
                                + ((lane >> 3) & 1) * 16);
    uint32_t Bh = smem_base + BH_OFF + nw * 48 * ROWB + b_off;

    int b_loc = tid >> 2;
    int h0 = (tid & 3) * 8;
    int bglob = bm0 + b_loc;
    // this thread's slice lands at this byte offset in every peer's A-next tile
    uint32_t slice_off = (uint32_t)(b_loc * ROWB + (hb0 + h0) * 2);
    float hprev[8];
#pragma unroll
    for (int j = 0; j < 8; j++) hprev[j] = 0.0f;

    for (int t = 0; t < TT; t++) {
        uint32_t Acur = smem_base + ((t & 1) ? A1_OFF : A0_OFF)
                        + mw * 16 * ROWB + a_off;
        uint32_t Anext_base = ((t & 1) ? A0_OFF : A1_OFF);

        if (tid < 192) {
            int b = tid / 3, f = tid % 3;
            Xs[b * 3 + f] = g_reprs[((size_t)(bm0 + b) * TT + t) * 3 + f];
        }

        float acc[6][4];
#pragma unroll
        for (int f = 0; f < 6; f++)
#pragma unroll
            for (int q = 0; q < 4; q++) acc[f][q] = 0.0f;

#pragma unroll 4
        for (int ks = 0; ks < 16; ks++) {
            uint32_t koff = ks * 32;
            uint32_t ah[4], bh[3][4];
            ldm4(ah, Acur + koff);
#pragma unroll
            for (int f = 0; f < 3; f++) ldm4(bh[f], Bh + f * 16 * ROWB + koff);
#pragma unroll
            for (int f = 0; f < 3; f++) {
                mma16816(acc[2 * f],     ah[0], ah[1], ah[2], ah[3], bh[f][0], bh[f][1]);
                mma16816(acc[2 * f + 1], ah[0], ah[1], ah[2], ah[3], bh[f][2], bh[f][3]);
            }
        }
        __syncthreads();

        {
            int mrow = mw * 16 + (lane >> 2);
            int ncol = nw * 48 + 2 * (lane & 3);
#pragma unroll
            for (int bf = 0; bf < 3; bf++)
#pragma unroll
                for (int sub = 0; sub < 2; sub++) {
                    float* c = acc[bf * 2 + sub];
                    int n = ncol + bf * 16 + sub * 8;
                    *(float2*)&ghs[mrow * 100 + n] = make_float2(c[0], c[1]);
                    *(float2*)&ghs[(mrow + 8) * 100 + n] = make_float2(c[2], c[3]);
                }
        }
        __syncthreads();

        float hf[8];
        uint4 phq;
        {
            float x0 = Xs[b_loc * 3], x1 = Xs[b_loc * 3 + 1], x2 = Xs[b_loc * 3 + 2];
            const float* gr = &ghs[b_loc * 100];
#pragma unroll
            for (int j = 0; j < 8; j++) {
                int hh = h0 + j;
                float ghr = gr[hh];
                float ghz = gr[32 + hh];
                float ghn = gr[64 + hh];
                const float* wr = &wihs[(0 * 32 + hh) * 3];
                const float* wz = &wihs[(1 * 32 + hh) * 3];
                const float* wn = &wihs[(2 * 32 + hh) * 3];
                float gi_r = fmaf(x2, wr[2], fmaf(x1, wr[1], x0 * wr[0])) + bihs[hh];
                float gi_z = fmaf(x2, wz[2], fmaf(x1, wz[1], x0 * wz[0])) + bihs[32 + hh];
                float gi_n = fmaf(x2, wn[2], fmaf(x1, wn[1], x0 * wn[0])) + bihs[64 + hh];
                float r = sigf(gi_r + ghr + bhhs[hh]);
                float z = sigf(gi_z + ghz + bhhs[32 + hh]);
                float n = tanhf_fast(gi_n + r * (ghn + bhhs[64 + hh]));
                float hn = n + z * (hprev[j] - n);
                hprev[j] = hn;
                hf[j] = hn;
            }
            __half2 ph[4];
#pragma unroll
            for (int j = 0; j < 4; j++)
                ph[j] = __floats2half2_rn(hf[2 * j], hf[2 * j + 1]);
            phq = make_uint4(*(uint32_t*)&ph[0], *(uint32_t*)&ph[1],
                             *(uint32_t*)&ph[2], *(uint32_t*)&ph[3]);
        }

        // push h slice into all 8 peers' A-next tiles (incl. self)
        if (t < TT - 1) {
            uint32_t dstl = smem_base + Anext_base + slice_off;
#pragma unroll
            for (uint32_t r = 0; r < 8; r++)
                st_cluster_v4(mapa_rank(dstl, r), phq);
        }
        // non-blocking global outputs
        *(uint4*)&g_enc16[((size_t)bglob * TT + t) * HH + hb0 + h0] = phq;
        if (t == TT - 1) {
            float* hd = &g_h1[(size_t)bglob * HH + hb0 + h0];
            *(float4*)&hd[0] = make_float4(hf[0], hf[1], hf[2], hf[3]);
            *(float4*)&hd[4] = make_float4(hf[4], hf[5], hf[6], hf[7]);
        }

        cluster_sync();   // peers' writes visible; all reads of Acur done
    }
}

// ---------------- eproj via mma.sync (unchanged) ----------------
#define EP_SMEM (2 * 64 * ROWB)

__global__ __launch_bounds__(256) void eproj_kernel() {
    extern __shared__ __align__(16) char sm[];
    uint32_t sb = smem_u32(sm);
    char* smA = sm;
    char* smB = sm + 64 * ROWB;
    int tid = threadIdx.x, wid = tid >> 5, lane = tid & 31;
    int m0 = blockIdx.x * 64, n0 = blockIdx.y * 64;

    for (int i = tid; i < 2048; i += 256) {
        int r = i >> 5, kc = i & 31;
        *(uint4*)(smA + r * ROWB + kc * 16) =
            *(const uint4*)&g_enc16[(size_t)(m0 + r) * HH + kc * 8];
        *(uint4*)(smB + r * ROWB + kc * 16) =
            *(const uint4*)&g_wte16[(size_t)(n0 + r) * HH + kc * 8];
    }
    __syncthreads();

    int mw = wid >> 1, nw = wid & 1;
    uint32_t a_off = (uint32_t)(((lane & 7) + ((lane >> 3) & 1) * 8) * ROWB
                                + ((lane >> 4) & 1) * 16);
    uint32_t b_off = (uint32_t)(((lane & 7) + ((lane >> 4) & 1) * 8) * ROWB
                                + ((lane >> 3) & 1) * 16);
    uint32_t Ah = sb + mw * 16 * ROWB + a_off;
    uint32_t Bh = sb + 64 * ROWB + nw * 32 * ROWB + b_off;

    float acc[4][4];
#pragma unroll
    for (int f = 0; f < 4; f++)
#pragma unroll
        for (int q = 0; q < 4; q++) acc[f][q] = 0.0f;

#pragma unroll 4
    for (int ks = 0; ks < 16; ks++) {
        uint32_t koff = ks * 32;
        uint32_t ah[4], bh[2][4];
        ldm4(ah, Ah + koff);
        ldm4(bh[0], Bh + koff);
        ldm4(bh[1], Bh + 16 * ROWB + koff);
#pragma unroll
        for (int f = 0; f < 2; f++) {
            mma16816(acc[2 * f],     ah[0], ah[1], ah[2], ah[3], bh[f][0], bh[f][1]);
            mma16816(acc[2 * f + 1], ah[0], ah[1], ah[2], ah[3], bh[f][2], bh[f][3]);
        }
    }

    int mrow = m0 + mw * 16 + (lane >> 2);
    int ncol = n0 + nw * 32 + 2 * (lane & 3);
#pragma unroll
    for (int f = 0; f < 2; f++)
#pragma unroll
        for (int sub = 0; sub < 2; sub++) {
            float* c = acc[2 * f + sub];
            int n = ncol + f * 16 + sub * 8;
            *(__half2*)&g_eproj16[(size_t)mrow * HH + n] =
                __floats2half2_rn(c[0], c[1]);
            *(__half2*)&g_eproj16[(size_t)(mrow + 8) * HH + n] =
                __floats2half2_rn(c[2], c[3]);
        }
}

// ---------------- fused decoder attention (R14, unchanged) ----------------
__global__ __launch_bounds__(256) void dec_attn2_kernel(
        const float* __restrict__ vt, const float* __restrict__ bt,
        const float* __restrict__ Wfc, const float* __restrict__ bfc,
        float* __restrict__ out, int s) {
    int b = blockIdx.x, tid = threadIdx.x;
    int wid = tid >> 5, lane = tid & 31;
    __shared__ float hs[HH], dps[HH], tws[TT], red[256];
    __shared__ float wred[8 * 256];
    const float* hin = (s == 0) ? g_h1 : g_hd[s & 1];
    hs[tid] = hin[(size_t)b * HH + tid];
    __syncthreads();

    if (s > 0) {
        float p = 0.0f;
#pragma unroll
        for (int i = 0; i < 8; i++) {
            int k = lane + 32 * i;
            p += hs[k] * Wfc[(size_t)wid * HH + k];
        }
        p = warp_sum(p);
        if (lane == 0) {
            float pv = p + bfc[wid];
            out[((size_t)b * PL + (s - 1)) * OUTD + wid] = pv;
            g_inp[b * INPAD + wid] = pv;
        }
        if (wid == 0) {
            float p8 = 0.0f;
#pragma unroll
            for (int i = 0; i < 8; i++) {
                int k = lane + 32 * i;
                p8 += hs[k] * Wfc[(size_t)8 * HH + k];
            }
            p8 = warp_sum(p8);
            if (lane == 0) {
                float pv = p8 + bfc[8];
                out[((size_t)b * PL + (s - 1)) * OUTD + 8] = pv;
                g_inp[b * INPAD + 8] = pv;
            }
        }
    }

    {
        float acc = 0.0f;
#pragma unroll 8
        for (int k = 0; k < HH; k++)
            acc = fmaf(hs[k], __half2float(g_wtdT16[(size_t)k * HH + tid]), acc);
        dps[tid] = acc + bt[tid];
    }
    __syncthreads();

    float dpr[8], vtr[8];
#pragma unroll
    for (int q = 0; q < 8; q++) {
        dpr[q] = dps[lane * 8 + q];
        vtr[q] = vt[lane * 8 + q];
    }
    const __half* ep = &g_eproj16[(size_t)b * TT * HH];
#pragma unroll 4
    for (int tl = 0; tl < 32; tl++) {
        int t = tl * 8 + wid;
        uint4 v = *(const uint4*)&ep[(size_t)t * HH + lane * 8];
        const __half2* h2 = (const __half2*)&v;
        float sv = 0.0f;
#pragma unroll
        for (int p = 0; p < 4; p++) {
            float2 cf = __half22float2(h2[p]);
            sv += tanh_apx(cf.x + dpr[2 * p]) * vtr[2 * p];
            sv += tanh_apx(cf.y + dpr[2 * p + 1]) * vtr[2 * p + 1];
        }
        sv = warp_sum(sv);
        if (lane == 0) tws[t] = sv;
    }
    __syncthreads();

    float v = tws[tid];
    red[tid] = v;
    __syncthreads();
    for (int o = 128; o > 0; o >>= 1) {
        if (tid < o) red[tid] = fmaxf(red[tid], red[tid + o]);
        __syncthreads();
    }
    float m = red[0];
    __syncthreads();
    float e = ex2f((v - m) * 1.4426950408889634f);
    red[tid] = e;
    __syncthreads();
    for (int o = 128; o > 0; o >>= 1) {
        if (tid < o) red[tid] += red[tid + o];
        __syncthreads();
    }
    float inv = frcp(red[0]);
    __syncthreads();
    tws[tid] = e * inv;
    __syncthreads();

    float ctx[8];
#pragma unroll
    for (int q = 0; q < 8; q++) ctx[q] = 0.0f;
    const __half* en = &g_enc16[(size_t)b * TT * HH];
#pragma unroll 4
    for (int tl = 0; tl < 32; tl++) {
        int t = tl * 8 + wid;
        uint4 v4 = *(const uint4*)&en[(size_t)t * HH + lane * 8];
        const __half2* h2 = (const __half2*)&v4;
        float ww = tws[t];
#pragma unroll
        for (int p = 0; p < 4; p++) {
            float2 cf = __half22float2(h2[p]);
            ctx[2 * p] = fmaf(ww, cf.x, ctx[2 * p]);
            ctx[2 * p + 1] = fmaf(ww, cf.y, ctx[2 * p + 1]);
        }
    }
#pragma unroll
    for (int q = 0; q < 8; q++) wred[wid * 256 + lane * 8 + q] = ctx[q];
    __syncthreads();
    {
        float a = 0.0f;
#pragma unroll
        for (int w = 0; w < 8; w++) a += wred[w * 256 + tid];
        g_inp[b * INPAD + OUTD + tid] = a;
    }
}

// ---------------- decoder GRU via mma.sync (R12, unchanged) ----------------
#define ROWB2 1088
#define GA_OFF 0
#define GB_OFF (64 * ROWB2)
#define GBI_OFF (GB_OFF + 128 * ROWB2)
#define GRU_SMEM (GBI_OFF + 128 * 4)

__global__ __launch_bounds__(256, 1) void dec_gru_mma(
        const float* __restrict__ bih, const float* __restrict__ bhh, int s) {
    extern __shared__ __align__(16) char sm[];
    uint32_t sb = smem_u32(sm);
    float* ghs = (float*)(sm + GA_OFF);
    float* bia = (float*)(sm + GBI_OFF);

    int tid = threadIdx.x;
    int wid = tid >> 5, lane = tid & 31;
    int bm0 = blockIdx.x * 64;
    int hg = blockIdx.y;
    int hb0 = hg * 32;

    const float* hin = (s == 0) ? g_h1 : g_hd[s & 1];
    float* hout = g_hd[(s + 1) & 1];

    if (tid < 32) {
        bia[tid]      = bih[0 * 256 + hb0 + tid] + bhh[0 * 256 + hb0 + tid];
        bia[32 + tid] = bih[1 * 256 + hb0 + tid] + bhh[1 * 256 + hb0 + tid];
        bia[64 + tid] = bih[2 * 256 + hb0 + tid];
        bia[96 + tid] = bhh[2 * 256 + hb0 + tid];
    }

    const __half* wsrc = &g_wgru16[(size_t)hg * 128 * 528];
    for (int i = tid; i < 128 * 66; i += 256) {
        int row = i / 66, c = i - row * 66;
        *(uint4*)(sm + GB_OFF + row * ROWB2 + c * 16) =
            *(const uint4*)&wsrc[(size_t)row * 528 + c * 8];
    }
    for (int i = tid; i < 64 * 66; i += 256) {
        int row = i / 66, c = i - row * 66;
        float f[8];
        if (c < 32) {
            const float* src = &hin[(size_t)(bm0 + row) * HH + c * 8];
#pragma unroll
            for (int q = 0; q < 8; q++) f[q] = src[q];
        } else {
            const float* src = &g_inp[(size_t)(bm0 + row) * INPAD + (c - 32) * 8];
#pragma unroll
            for (int q = 0; q < 8; q++) f[q] = src[q];
        }
        __half2 h2[4];
#pragma unroll
        for (int q = 0; q < 4; q++) h2[q] = __floats2half2_rn(f[2 * q], f[2 * q + 1]);
        *(uint4*)(sm + GA_OFF + row * ROWB2 + c * 16) =
            make_uint4(*(uint32_t*)&h2[0], *(uint32_t*)&h2[1],
                       *(uint32_t*)&h2[2], *(uint32_t*)&h2[3]);
    }
    __syncthreads();

    int mw = wid >> 1, nw = wid & 1;
    uint32_t a_off = (uint32_t)(((lane & 7) + ((lane >> 3) & 1) * 8) * ROWB2
                                + ((lane >> 4) & 1) * 16);
    uint32_t b_off = (uint32_t)(((lane & 7) + ((lane >> 4) & 1) * 8) * ROWB2
                                + ((lane >> 3) & 1) * 16);
    uint32_t Ah = sb + GA_OFF + mw * 16 * ROWB2 + a_off;
    uint32_t Bh = sb + GB_OFF + nw * 64 * ROWB2 + b_off;

    float acc[8][4];
#pragma unroll
    for (int f = 0; f < 8; f++)
#pragma unroll
        for (int q = 0; q < 4; q++) acc[f][q] = 0.0f;

#pragma unroll 3
    for (int ks = 0; ks < 33; ks++) {
        uint32_t koff = ks * 32;
        uint32_t ah[4], bh[4][4];
        ldm4(ah, Ah + koff);
#pragma unroll
        for (int f = 0; f < 4; f++) ldm4(bh[f], Bh + f * 16 * ROWB2 + koff);
#pragma unroll
        for (int f = 0; f < 4; f++) {
            mma16816(acc[2 * f],     ah[0], ah[1], ah[2], ah[3], bh[f][0], bh[f][1]);
            mma16816(acc[2 * f + 1], ah[0], ah[1], ah[2], ah[3], bh[f][2], bh[f][3]);
        }
    }
    __syncthreads();

    {
        int mrow = mw * 16 + (lane >> 2);
        int ncol = nw * 64 + 2 * (lane & 3);
#pragma unroll
        for (int f = 0; f < 4; f++)
#pragma unroll
            for (int sub = 0; sub < 2; sub++) {
                float* c = acc[2 * f + sub];
                int n = ncol + f * 16 + sub * 8;
                *(float2*)&ghs[mrow * 132 + n] = make_float2(c[0], c[1]);
                *(float2*)&ghs[(mrow + 8) * 132 + n] = make_float2(c[2], c[3]);
            }
    }
    __syncthreads();

    int b_loc = tid >> 2;
    int h0 = (tid & 3) * 8;
    int b = bm0 + b_loc;
    const float* gr = &ghs[b_loc * 132];
#pragma unroll
    for (int j = 0; j < 8; j++) {
        int hh = h0 + j;
        float r = sigf(gr[hh] + bia[hh]);
        float z = sigf(gr[32 + hh] + bia[32 + hh]);
        float n = tanhf_fast(gr[96 + hh] + bia[64 + hh] + r * (gr[64 + hh] + bia[96 + hh]));
        float hp = hin[(size_t)b * HH + hb0 + hh];
        hout[(size_t)b * HH + hb0 + hh] = n + z * (hp - n);
    }
}

// ---------------- final prediction head ----------------
__global__ __launch_bounds__(288) void pred_kernel(
        const float* __restrict__ Wfc, const float* __restrict__ bfc,
        float* __restrict__ out, int s) {
    int b = blockIdx.x, tid = threadIdx.x;
    const float* h = &g_hd[(s + 1) & 1][(size_t)b * HH];
    __shared__ float hs[HH];
    if (tid < HH) hs[tid] = h[tid];
    __syncthreads();
    int w = tid >> 5, lane = tid & 31;
    float sacc = 0.0f;
#pragma unroll
    for (int i = 0; i < 8; i++) {
        int hh = lane + 32 * i;
        sacc += hs[hh] * Wfc[w * HH + hh];
    }
    sacc = warp_sum(sacc);
    if (lane == 0) {
        out[((size_t)b * PL + s) * OUTD + w] = sacc + bfc[w];
    }
}

// ---------------- host orchestration ----------------
extern "C" void kernel_launch(void* const* d_in, const int* in_sizes, int n_in,
                              void* d_out, int out_size) {
    const float* x    = (const float*)d_in[0];
    const float* Wa   = (const float*)d_in[1];
    const float* ba   = (const float*)d_in[2];
    const float* va   = (const float*)d_in[3];
    const float* eWih = (const float*)d_in[4];
    const float* eWhh = (const float*)d_in[5];
    const float* ebih = (const float*)d_in[6];
    const float* ebhh = (const float*)d_in[7];
    const float* dWih = (const float*)d_in[8];
    const float* dWhh = (const float*)d_in[9];
    const float* dbih = (const float*)d_in[10];
    const float* dbhh = (const float*)d_in[11];
    const float* Wt   = (const float*)d_in[12];
    const float* bt   = (const float*)d_in[13];
    const float* vt   = (const float*)d_in[14];
    const float* Wfc  = (const float*)d_in[15];
    const float* bfc  = (const float*)d_in[16];
    float* out = (float*)d_out;

    init_a_kernel<<<256, 256>>>(x);
    init_w_kernel<<<256, 256>>>(Wt, dWih, dWhh);
    agent_attn_kernel<<<(BB * TT) / 8, 256>>>(x, Wa, ba, va);

    cudaFuncSetAttribute(enc_persistent,
                         cudaFuncAttributeMaxDynamicSharedMemorySize, ENC_SMEM);
    enc_persistent<<<128, 256, ENC_SMEM>>>(eWhh, eWih, ebih, ebhh);

    cudaFuncSetAttribute(eproj_kernel,
                         cudaFuncAttributeMaxDynamicSharedMemorySize, EP_SMEM);
    eproj_kernel<<<dim3((BB * TT) / 64, HH / 64), 256, EP_SMEM>>>();

    cudaFuncSetAttribute(dec_gru_mma,
                         cudaFuncAttributeMaxDynamicSharedMemorySize, GRU_SMEM);
    for (int s = 0; s < PL; s++) {
        dec_attn2_kernel<<<BB, 256>>>(vt, bt, Wfc, bfc, out, s);
        dec_gru_mma<<<dim3(16, 8), 256, GRU_SMEM>>>(dbih, dbhh, s);
    }
    pred_kernel<<<BB, 288>>>(Wfc, bfc, out, PL - 1);
}

// round 17
// speedup vs baseline: 1.4451x; 1.4451x over previous
#include <cuda_runtime.h>
#include <cuda_fp16.h>
#include <cstdint>

#define BB 1024
#define TT 256
#define HH 256
#define OUTD 9
#define PL 16
#define INPAD 272   // 9 + 256 = 265, padded to 272

typedef unsigned long long u64;

// ---------------- device scratch ----------------
__device__ __align__(16) float g_reprs[BB * TT * 3];
__device__ __align__(16) __half g_enc16[(size_t)BB * TT * HH];
__device__ __align__(16) __half g_eproj16[(size_t)BB * TT * HH];
__device__ __align__(16) __half g_hx[2][BB * HH];     // fp16 h exchange ping-pong
__device__ __align__(16) float g_h1[BB * HH];         // final encoder h (fp32)
__device__ __align__(16) float g_hd[2][BB * HH];
__device__ __align__(16) float g_inp[BB * INPAD];
__device__ __align__(16) __half g_wtdT16[HH * HH];    // transposed Wt_dec fp16
__device__ __align__(16) __half g_wte16[HH * HH];
__device__ __align__(16) __half g_wgru16[8 * 128 * 528];  // [hg][128 rows][528 k]
__device__ unsigned g_barcnt[16];

// ---------------- math helpers ----------------
__device__ __forceinline__ float ex2f(float x) {
    float r; asm("ex2.approx.f32 %0, %1;" : "=f"(r) : "f"(x)); return r;
}
__device__ __forceinline__ float frcp(float x) {
    float r; asm("rcp.approx.f32 %0, %1;" : "=f"(r) : "f"(x)); return r;
}
__device__ __forceinline__ float sigf(float x) {
    return frcp(1.0f + ex2f(-1.4426950408889634f * x));
}
__device__ __forceinline__ float tanhf_fast(float x) {
    float ax = fabsf(x);
    float e = ex2f(-2.8853900817779268f * ax);
    float r = (1.0f - e) * frcp(1.0f + e);
    return copysignf(r, x);
}
__device__ __forceinline__ float tanh_apx(float x) {
    float r; asm("tanh.approx.f32 %0, %1;" : "=f"(r) : "f"(x)); return r;
}
__device__ __forceinline__ float warp_sum(float v) {
#pragma unroll
    for (int o = 16; o > 0; o >>= 1) v += __shfl_xor_sync(0xffffffffu, v, o);
    return v;
}
__device__ __forceinline__ unsigned ld_acq(const unsigned* p) {
    unsigned v;
    asm volatile("ld.acquire.gpu.u32 %0, [%1];" : "=r"(v) : "l"(p));
    return v;
}
__device__ __forceinline__ void red_release_add(unsigned* p, unsigned v) {
    asm volatile("red.release.gpu.global.add.u32 [%0], %1;" :: "l"(p), "r"(v) : "memory");
}
__device__ __forceinline__ uint32_t smem_u32(const void* p) {
    uint32_t a;
    asm("{ .reg .u64 t; cvta.to.shared.u64 t, %1; cvt.u32.u64 %0, t; }"
        : "=r"(a) : "l"(p));
    return a;
}
__device__ __forceinline__ void ldm4(uint32_t* r, uint32_t addr) {
    asm volatile("ldmatrix.sync.aligned.m8n8.x4.shared.b16 {%0,%1,%2,%3}, [%4];"
        : "=r"(r[0]), "=r"(r[1]), "=r"(r[2]), "=r"(r[3]) : "r"(addr));
}
__device__ __forceinline__ void mma16816(float* c,
        uint32_t a0, uint32_t a1, uint32_t a2, uint32_t a3,
        uint32_t b0, uint32_t b1) {
    asm volatile(
        "mma.sync.aligned.m16n8k16.row.col.f32.f16.f16.f32 "
        "{%0,%1,%2,%3}, {%4,%5,%6,%7}, {%8,%9}, {%0,%1,%2,%3};"
        : "+f"(c[0]), "+f"(c[1]), "+f"(c[2]), "+f"(c[3])
        : "r"(a0), "r"(a1), "r"(a2), "r"(a3), "r"(b0), "r"(b1));
}

// ---------------- init ----------------
__global__ void init_a_kernel(const float* __restrict__ x) {
    int idx = blockIdx.x * blockDim.x + threadIdx.x;
    int stride = gridDim.x * blockDim.x;
    if (idx < 16) g_barcnt[idx] = 0u;
    for (int i = idx; i < BB * INPAD; i += stride) {
        int b = i / INPAD, c = i - b * INPAD;
        g_inp[i] = (c < OUTD) ? x[((size_t)b * TT + (TT - 1)) * OUTD + c] : 0.0f;
    }
}
// merged weight prep (Wt halves + decoder GRU pack)
__global__ void init_w_kernel(const float* __restrict__ Wt,
                              const float* __restrict__ dWih,
                              const float* __restrict__ dWhh) {
    int idx = blockIdx.x * blockDim.x + threadIdx.x;
    int stride = gridDim.x * blockDim.x;
    for (int i = idx; i < HH * HH; i += stride) {
        int k = i >> 8, n = i & 255;
        g_wtdT16[i] = __float2half_rn(Wt[n * (2 * HH) + k]);
        int g = i >> 8, c = i & 255;
        g_wte16[i] = __float2half_rn(Wt[g * (2 * HH) + HH + c]);
    }
    const int TOT = 8 * 128 * 528;
    for (int i = idx; i < TOT; i += stride) {
        int hg = i / (128 * 528);
        int rem = i - hg * (128 * 528);
        int row = rem / 528;
        int k = rem - row * 528;
        int cls = row >> 5, hh = row & 31;
        int gr = hg * 32 + hh;
        float v = 0.0f;
        if (cls == 0) {
            v = (k < 256) ? dWhh[(size_t)(0 * 256 + gr) * 256 + k]
                : ((k - 256 < 265) ? dWih[(size_t)(0 * 256 + gr) * 265 + (k - 256)] : 0.0f);
        } else if (cls == 1) {
            v = (k < 256) ? dWhh[(size_t)(1 * 256 + gr) * 256 + k]
                : ((k - 256 < 265) ? dWih[(size_t)(1 * 256 + gr) * 265 + (k - 256)] : 0.0f);
        } else if (cls == 2) {
            v = (k < 256) ? dWhh[(size_t)(2 * 256 + gr) * 256 + k] : 0.0f;
        } else {
            v = (k >= 256 && k - 256 < 265) ? dWih[(size_t)(2 * 256 + gr) * 265 + (k - 256)] : 0.0f;
        }
        g_wgru16[i] = __float2half_rn(v);
    }
}

// ---------------- stage 1: agent attention (tanh.approx) ----------------
__global__ __launch_bounds__(256) void agent_attn_kernel(
        const float* __restrict__ x, const float* __restrict__ Wa,
        const float* __restrict__ ba, const float* __restrict__ va) {
    __shared__ float Was[HH * 3];
    __shared__ float vas[HH];
    __shared__ float bas[HH];
    int tid = threadIdx.x;
    for (int i = tid; i < HH * 3; i += 256) Was[i] = Wa[i];
    vas[tid] = va[tid];
    bas[tid] = ba[tid];
    __syncthreads();

    int pair = blockIdx.x * 8 + (tid >> 5);
    int lane = tid & 31;
    const float* xp = &x[(size_t)pair * 9];
    float xv[9];
#pragma unroll
    for (int i = 0; i < 9; i++) xv[i] = xp[i];

    float sc[3];
#pragma unroll
    for (int a = 0; a < 3; a++) {
        float s = 0.0f;
        float x0 = xv[a * 3], x1 = xv[a * 3 + 1], x2 = xv[a * 3 + 2];
#pragma unroll
        for (int i = 0; i < 8; i++) {
            int h = lane + 32 * i;
            float e = tanh_apx(fmaf(x2, Was[h * 3 + 2],
                          fmaf(x1, Was[h * 3 + 1], x0 * Was[h * 3])) + bas[h]);
            s += e * vas[h];
        }
        sc[a] = warp_sum(s);
    }
    float m = fmaxf(sc[0], fmaxf(sc[1], sc[2]));
    float e0 = ex2f((sc[0] - m) * 1.4426950408889634f);
    float e1 = ex2f((sc[1] - m) * 1.4426950408889634f);
    float e2 = ex2f((sc[2] - m) * 1.4426950408889634f);
    float inv = frcp(e0 + e1 + e2);
    float a0 = e0 * inv, a1 = e1 * inv, a2 = e2 * inv;
    if (lane < 3) {
        g_reprs[pair * 3 + lane] =
            a0 * xv[lane] + a1 * xv[3 + lane] + a2 * xv[6 + lane];
    }
}

// ---------------- stage 2: mma.sync persistent encoder (R14 config) ----------------
#define ROWB 528
#define AHI_OFF 0
#define BHI_OFF (64 * ROWB)
#define GHS_OFF (BHI_OFF + 96 * ROWB)
#define XS_OFF  (GHS_OFF + 64 * 100 * 4)
#define WIH_OFF (XS_OFF + 192 * 4)
#define BIH_OFF (WIH_OFF + 288 * 4)
#define BHH_OFF (BIH_OFF + 96 * 4)
#define ENC_SMEM (BHH_OFF + 96 * 4)

__global__ __launch_bounds__(256, 1) void enc_persistent(
        const float* __restrict__ Whh, const float* __restrict__ Wih,
        const float* __restrict__ bih, const float* __restrict__ bhh) {
    extern __shared__ __align__(16) char smraw[];
    uint32_t smem_base = smem_u32(smraw);
    float* ghs  = (float*)(smraw + GHS_OFF);
    float* Xs   = (float*)(smraw + XS_OFF);
    float* wihs = (float*)(smraw + WIH_OFF);
    float* bihs = (float*)(smraw + BIH_OFF);
    float* bhhs = (float*)(smraw + BHH_OFF);

    int tid = threadIdx.x;
    int wid = tid >> 5, lane = tid & 31;
    int bid = blockIdx.x;
    int bg  = bid >> 3;
    int bm0 = bg * 64;
    int hb0 = (bid & 7) * 32;

    for (int i = tid; i < (64 * ROWB) / 16; i += 256)
        ((uint4*)smraw)[i] = make_uint4(0, 0, 0, 0);

    for (int i = tid; i < 96 * 128; i += 256) {
        int n = i >> 7, kp = i & 127;
        int g = n >> 5, hh = n & 31;
        float2 w = *(const float2*)&Whh[(size_t)(g * HH + hb0 + hh) * HH + kp * 2];
        *(__half2*)(smraw + BHI_OFF + n * ROWB + kp * 4) = __floats2half2_rn(w.x, w.y);
    }
    for (int i = tid; i < 288; i += 256) {
        int g = i / 96, r = i % 96, hh = r / 3, f = r % 3;
        wihs[(g * 32 + hh) * 3 + f] = Wih[(size_t)(g * HH + hb0 + hh) * 3 + f];
    }
    if (tid < 96) {
        int g = tid >> 5, hh = tid & 31;
        bihs[g * 32 + hh] = bih[g * HH + hb0 + hh];
        bhhs[g * 32 + hh] = bhh[g * HH + hb0 + hh];
    }
    __syncthreads();

    int mw = wid >> 1, nw = wid & 1;
    uint32_t a_off = (uint32_t)(((lane & 7) + ((lane >> 3) & 1) * 8) * ROWB
                                + ((lane >> 4) & 1) * 16);
    uint32_t b_off = (uint32_t)(((lane & 7) + ((lane >> 4) & 1) * 8) * ROWB
                                + ((lane >> 3) & 1) * 16);
    uint32_t Ah = smem_base + AHI_OFF + mw * 16 * ROWB + a_off;
    uint32_t Bh = smem_base + BHI_OFF + nw * 48 * ROWB + b_off;

    int b_loc = tid >> 2;
    int h0 = (tid & 3) * 8;
    int bglob = bm0 + b_loc;
    float hprev[8];
#pragma unroll
    for (int j = 0; j < 8; j++) hprev[j] = 0.0f;

    for (int t = 0; t < TT; t++) {
        if (t > 0) {
            const __half* hsrc = g_hx[(t + 1) & 1];
            for (int i = tid; i < 2048; i += 256) {
                int r = i >> 5, kc = i & 31;
                uint4 v = __ldcg((const uint4*)&hsrc[(size_t)(bm0 + r) * HH + kc * 8]);
                *(uint4*)(smraw + AHI_OFF + r * ROWB + kc * 16) = v;
            }
        }
        if (tid < 192) {
            int b = tid / 3, f = tid % 3;
            Xs[b * 3 + f] = g_reprs[((size_t)(bm0 + b) * TT + t) * 3 + f];
        }
        __syncthreads();

        float acc[6][4];
#pragma unroll
        for (int f = 0; f < 6; f++)
#pragma unroll
            for (int q = 0; q < 4; q++) acc[f][q] = 0.0f;

#pragma unroll 4
        for (int ks = 0; ks < 16; ks++) {
            uint32_t koff = ks * 32;
            uint32_t ah[4], bh[3][4];
            ldm4(ah, Ah + koff);
#pragma unroll
            for (int f = 0; f < 3; f++) ldm4(bh[f], Bh + f * 16 * ROWB + koff);
#pragma unroll
            for (int f = 0; f < 3; f++) {
                mma16816(acc[2 * f],     ah[0], ah[1], ah[2], ah[3], bh[f][0], bh[f][1]);
                mma16816(acc[2 * f + 1], ah[0], ah[1], ah[2], ah[3], bh[f][2], bh[f][3]);
            }
        }

        {
            int mrow = mw * 16 + (lane >> 2);
            int ncol = nw * 48 + 2 * (lane & 3);
#pragma unroll
            for (int bf = 0; bf < 3; bf++)
#pragma unroll
                for (int sub = 0; sub < 2; sub++) {
                    float* c = acc[bf * 2 + sub];
                    int n = ncol + bf * 16 + sub * 8;
                    *(float2*)&ghs[mrow * 100 + n] = make_float2(c[0], c[1]);
                    *(float2*)&ghs[(mrow + 8) * 100 + n] = make_float2(c[2], c[3]);
                }
        }
        __syncthreads();

        float hf[8];
        uint4 phq;
        {
            float x0 = Xs[b_loc * 3], x1 = Xs[b_loc * 3 + 1], x2 = Xs[b_loc * 3 + 2];
            const float* gr = &ghs[b_loc * 100];
#pragma unroll
            for (int j = 0; j < 8; j++) {
                int hh = h0 + j;
                float ghr = gr[hh];
                float ghz = gr[32 + hh];
                float ghn = gr[64 + hh];
                const float* wr = &wihs[(0 * 32 + hh) * 3];
                const float* wz = &wihs[(1 * 32 + hh) * 3];
                const float* wn = &wihs[(2 * 32 + hh) * 3];
                float gi_r = fmaf(x2, wr[2], fmaf(x1, wr[1], x0 * wr[0])) + bihs[hh];
                float gi_z = fmaf(x2, wz[2], fmaf(x1, wz[1], x0 * wz[0])) + bihs[32 + hh];
                float gi_n = fmaf(x2, wn[2], fmaf(x1, wn[1], x0 * wn[0])) + bihs[64 + hh];
                float r = sigf(gi_r + ghr + bhhs[hh]);
                float z = sigf(gi_z + ghz + bhhs[32 + hh]);
                float n = tanhf_fast(gi_n + r * (ghn + bhhs[64 + hh]));
                float hn = n + z * (hprev[j] - n);
                hprev[j] = hn;
                hf[j] = hn;
            }
            __half2 ph[4];
#pragma unroll
            for (int j = 0; j < 4; j++)
                ph[j] = __floats2half2_rn(hf[2 * j], hf[2 * j + 1]);
            phq = make_uint4(*(uint32_t*)&ph[0], *(uint32_t*)&ph[1],
                             *(uint32_t*)&ph[2], *(uint32_t*)&ph[3]);
            *(uint4*)&g_hx[t & 1][(size_t)bglob * HH + hb0 + h0] = phq;
        }

        __syncthreads();
        if (tid == 0 && t < TT - 1) red_release_add(&g_barcnt[bg], 1u);
        {
            *(uint4*)&g_enc16[((size_t)bglob * TT + t) * HH + hb0 + h0] = phq;
            if (t == TT - 1) {
                float* hd = &g_h1[(size_t)bglob * HH + hb0 + h0];
                *(float4*)&hd[0] = make_float4(hf[0], hf[1], hf[2], hf[3]);
                *(float4*)&hd[4] = make_float4(hf[4], hf[5], hf[6], hf[7]);
            }
        }
        if (tid == 0 && t < TT - 1) {
            unsigned target = 8u * (unsigned)(t + 1);
            while (ld_acq(&g_barcnt[bg]) < target) { }
        }
        __syncthreads();
    }
}

// ---------------- eproj via mma.sync (unchanged) ----------------
#define EP_SMEM (2 * 64 * ROWB)

__global__ __launch_bounds__(256) void eproj_kernel() {
    extern __shared__ __align__(16) char sm[];
    uint32_t sb = smem_u32(sm);
    char* smA = sm;
    char* smB = sm + 64 * ROWB;
    int tid = threadIdx.x, wid = tid >> 5, lane = tid & 31;
    int m0 = blockIdx.x * 64, n0 = blockIdx.y * 64;

    for (int i = tid; i < 2048; i += 256) {
        int r = i >> 5, kc = i & 31;
        *(uint4*)(smA + r * ROWB + kc * 16) =
            *(const uint4*)&g_enc16[(size_t)(m0 + r) * HH + kc * 8];
        *(uint4*)(smB + r * ROWB + kc * 16) =
            *(const uint4*)&g_wte16[(size_t)(n0 + r) * HH + kc * 8];
    }
    __syncthreads();

    int mw = wid >> 1, nw = wid & 1;
    uint32_t a_off = (uint32_t)(((lane & 7) + ((lane >> 3) & 1) * 8) * ROWB
                                + ((lane >> 4) & 1) * 16);
    uint32_t b_off = (uint32_t)(((lane & 7) + ((lane >> 4) & 1) * 8) * ROWB
                                + ((lane >> 3) & 1) * 16);
    uint32_t Ah = sb + mw * 16 * ROWB + a_off;
    uint32_t Bh = sb + 64 * ROWB + nw * 32 * ROWB + b_off;

    float acc[4][4];
#pragma unroll
    for (int f = 0; f < 4; f++)
#pragma unroll
        for (int q = 0; q < 4; q++) acc[f][q] = 0.0f;

#pragma unroll 4
    for (int ks = 0; ks < 16; ks++) {
        uint32_t koff = ks * 32;
        uint32_t ah[4], bh[2][4];
        ldm4(ah, Ah + koff);
        ldm4(bh[0], Bh + koff);
        ldm4(bh[1], Bh + 16 * ROWB + koff);
#pragma unroll
        for (int f = 0; f < 2; f++) {
            mma16816(acc[2 * f],     ah[0], ah[1], ah[2], ah[3], bh[f][0], bh[f][1]);
            mma16816(acc[2 * f + 1], ah[0], ah[1], ah[2], ah[3], bh[f][2], bh[f][3]);
        }
    }

    int mrow = m0 + mw * 16 + (lane >> 2);
    int ncol = n0 + nw * 32 + 2 * (lane & 3);
#pragma unroll
    for (int f = 0; f < 2; f++)
#pragma unroll
        for (int sub = 0; sub < 2; sub++) {
            float* c = acc[2 * f + sub];
            int n = ncol + f * 16 + sub * 8;
            *(__half2*)&g_eproj16[(size_t)mrow * HH + n] =
                __floats2half2_rn(c[0], c[1]);
            *(__half2*)&g_eproj16[(size_t)(mrow + 8) * HH + n] =
                __floats2half2_rn(c[2], c[3]);
        }
}

// ---------------- fused decoder attention (R14, unchanged) ----------------
__global__ __launch_bounds__(256) void dec_attn2_kernel(
        const float* __restrict__ vt, const float* __restrict__ bt,
        const float* __restrict__ Wfc, const float* __restrict__ bfc,
        float* __restrict__ out, int s) {
    int b = blockIdx.x, tid = threadIdx.x;
    int wid = tid >> 5, lane = tid & 31;
    __shared__ float hs[HH], dps[HH], tws[TT], red[256];
    __shared__ float wred[8 * 256];
    const float* hin = (s == 0) ? g_h1 : g_hd[s & 1];
    hs[tid] = hin[(size_t)b * HH + tid];
    __syncthreads();

    if (s > 0) {
        float p = 0.0f;
#pragma unroll
        for (int i = 0; i < 8; i++) {
            int k = lane + 32 * i;
            p += hs[k] * Wfc[(size_t)wid * HH + k];
        }
        p = warp_sum(p);
        if (lane == 0) {
            float pv = p + bfc[wid];
            out[((size_t)b * PL + (s - 1)) * OUTD + wid] = pv;
            g_inp[b * INPAD + wid] = pv;
        }
        if (wid == 0) {
            float p8 = 0.0f;
#pragma unroll
            for (int i = 0; i < 8; i++) {
                int k = lane + 32 * i;
                p8 += hs[k] * Wfc[(size_t)8 * HH + k];
            }
            p8 = warp_sum(p8);
            if (lane == 0) {
                float pv = p8 + bfc[8];
                out[((size_t)b * PL + (s - 1)) * OUTD + 8] = pv;
                g_inp[b * INPAD + 8] = pv;
            }
        }
    }

    {
        float acc = 0.0f;
#pragma unroll 8
        for (int k = 0; k < HH; k++)
            acc = fmaf(hs[k], __half2float(g_wtdT16[(size_t)k * HH + tid]), acc);
        dps[tid] = acc + bt[tid];
    }
    __syncthreads();

    float dpr[8], vtr[8];
#pragma unroll
    for (int q = 0; q < 8; q++) {
        dpr[q] = dps[lane * 8 + q];
        vtr[q] = vt[lane * 8 + q];
    }
    const __half* ep = &g_eproj16[(size_t)b * TT * HH];
#pragma unroll 4
    for (int tl = 0; tl < 32; tl++) {
        int t = tl * 8 + wid;
        uint4 v = *(const uint4*)&ep[(size_t)t * HH + lane * 8];
        const __half2* h2 = (const __half2*)&v;
        float sv = 0.0f;
#pragma unroll
        for (int p = 0; p < 4; p++) {
            float2 cf = __half22float2(h2[p]);
            sv += tanh_apx(cf.x + dpr[2 * p]) * vtr[2 * p];
            sv += tanh_apx(cf.y + dpr[2 * p + 1]) * vtr[2 * p + 1];
        }
        sv = warp_sum(sv);
        if (lane == 0) tws[t] = sv;
    }
    __syncthreads();

    float v = tws[tid];
    red[tid] = v;
    __syncthreads();
    for (int o = 128; o > 0; o >>= 1) {
        if (tid < o) red[tid] = fmaxf(red[tid], red[tid + o]);
        __syncthreads();
    }
    float m = red[0];
    __syncthreads();
    float e = ex2f((v - m) * 1.4426950408889634f);
    red[tid] = e;
    __syncthreads();
    for (int o = 128; o > 0; o >>= 1) {
        if (tid < o) red[tid] += red[tid + o];
        __syncthreads();
    }
    float inv = frcp(red[0]);
    __syncthreads();
    tws[tid] = e * inv;
    __syncthreads();

    float ctx[8];
#pragma unroll
    for (int q = 0; q < 8; q++) ctx[q] = 0.0f;
    const __half* en = &g_enc16[(size_t)b * TT * HH];
#pragma unroll 4
    for (int tl = 0; tl < 32; tl++) {
        int t = tl * 8 + wid;
        uint4 v4 = *(const uint4*)&en[(size_t)t * HH + lane * 8];
        const __half2* h2 = (const __half2*)&v4;
        float ww = tws[t];
#pragma unroll
        for (int p = 0; p < 4; p++) {
            float2 cf = __half22float2(h2[p]);
            ctx[2 * p] = fmaf(ww, cf.x, ctx[2 * p]);
            ctx[2 * p + 1] = fmaf(ww, cf.y, ctx[2 * p + 1]);
        }
    }
#pragma unroll
    for (int q = 0; q < 8; q++) wred[wid * 256 + lane * 8 + q] = ctx[q];
    __syncthreads();
    {
        float a = 0.0f;
#pragma unroll
        for (int w = 0; w < 8; w++) a += wred[w * 256 + tid];
        g_inp[b * INPAD + OUTD + tid] = a;
    }
}

// ---------------- decoder GRU via mma.sync (R12, unchanged) ----------------
#define ROWB2 1088
#define GA_OFF 0
#define GB_OFF (64 * ROWB2)
#define GBI_OFF (GB_OFF + 128 * ROWB2)
#define GRU_SMEM (GBI_OFF + 128 * 4)

__global__ __launch_bounds__(256, 1) void dec_gru_mma(
        const float* __restrict__ bih, const float* __restrict__ bhh, int s) {
    extern __shared__ __align__(16) char sm[];
    uint32_t sb = smem_u32(sm);
    float* ghs = (float*)(sm + GA_OFF);
    float* bia = (float*)(sm + GBI_OFF);

    int tid = threadIdx.x;
    int wid = tid >> 5, lane = tid & 31;
    int bm0 = blockIdx.x * 64;
    int hg = blockIdx.y;
    int hb0 = hg * 32;

    const float* hin = (s == 0) ? g_h1 : g_hd[s & 1];
    float* hout = g_hd[(s + 1) & 1];

    if (tid < 32) {
        bia[tid]      = bih[0 * 256 + hb0 + tid] + bhh[0 * 256 + hb0 + tid];
        bia[32 + tid] = bih[1 * 256 + hb0 + tid] + bhh[1 * 256 + hb0 + tid];
        bia[64 + tid] = bih[2 * 256 + hb0 + tid];
        bia[96 + tid] = bhh[2 * 256 + hb0 + tid];
    }

    const __half* wsrc = &g_wgru16[(size_t)hg * 128 * 528];
    for (int i = tid; i < 128 * 66; i += 256) {
        int row = i / 66, c = i - row * 66;
        *(uint4*)(sm + GB_OFF + row * ROWB2 + c * 16) =
            *(const uint4*)&wsrc[(size_t)row * 528 + c * 8];
    }
    for (int i = tid; i < 64 * 66; i += 256) {
        int row = i / 66, c = i - row * 66;
        float f[8];
        if (c < 32) {
            const float* src = &hin[(size_t)(bm0 + row) * HH + c * 8];
#pragma unroll
            for (int q = 0; q < 8; q++) f[q] = src[q];
        } else {
            const float* src = &g_inp[(size_t)(bm0 + row) * INPAD + (c - 32) * 8];
#pragma unroll
            for (int q = 0; q < 8; q++) f[q] = src[q];
        }
        __half2 h2[4];
#pragma unroll
        for (int q = 0; q < 4; q++) h2[q] = __floats2half2_rn(f[2 * q], f[2 * q + 1]);
        *(uint4*)(sm + GA_OFF + row * ROWB2 + c * 16) =
            make_uint4(*(uint32_t*)&h2[0], *(uint32_t*)&h2[1],
                       *(uint32_t*)&h2[2], *(uint32_t*)&h2[3]);
    }
    __syncthreads();

    int mw = wid >> 1, nw = wid & 1;
    uint32_t a_off = (uint32_t)(((lane & 7) + ((lane >> 3) & 1) * 8) * ROWB2
                                + ((lane >> 4) & 1) * 16);
    uint32_t b_off = (uint32_t)(((lane & 7) + ((lane >> 4) & 1) * 8) * ROWB2
                                + ((lane >> 3) & 1) * 16);
    uint32_t Ah = sb + GA_OFF + mw * 16 * ROWB2 + a_off;
    uint32_t Bh = sb + GB_OFF + nw * 64 * ROWB2 + b_off;

    float acc[8][4];
#pragma unroll
    for (int f = 0; f < 8; f++)
#pragma unroll
        for (int q = 0; q < 4; q++) acc[f][q] = 0.0f;

#pragma unroll 3
    for (int ks = 0; ks < 33; ks++) {
        uint32_t koff = ks * 32;
        uint32_t ah[4], bh[4][4];
        ldm4(ah, Ah + koff);
#pragma unroll
        for (int f = 0; f < 4; f++) ldm4(bh[f], Bh + f * 16 * ROWB2 + koff);
#pragma unroll
        for (int f = 0; f < 4; f++) {
            mma16816(acc[2 * f],     ah[0], ah[1], ah[2], ah[3], bh[f][0], bh[f][1]);
            mma16816(acc[2 * f + 1], ah[0], ah[1], ah[2], ah[3], bh[f][2], bh[f][3]);
        }
    }
    __syncthreads();

    {
        int mrow = mw * 16 + (lane >> 2);
        int ncol = nw * 64 + 2 * (lane & 3);
#pragma unroll
        for (int f = 0; f < 4; f++)
#pragma unroll
            for (int sub = 0; sub < 2; sub++) {
                float* c = acc[2 * f + sub];
                int n = ncol + f * 16 + sub * 8;
                *(float2*)&ghs[mrow * 132 + n] = make_float2(c[0], c[1]);
                *(float2*)&ghs[(mrow + 8) * 132 + n] = make_float2(c[2], c[3]);
            }
    }
    __syncthreads();

    int b_loc = tid >> 2;
    int h0 = (tid & 3) * 8;
    int b = bm0 + b_loc;
    const float* gr = &ghs[b_loc * 132];
#pragma unroll
    for (int j = 0; j < 8; j++) {
        int hh = h0 + j;
        float r = sigf(gr[hh] + bia[hh]);
        float z = sigf(gr[32 + hh] + bia[32 + hh]);
        float n = tanhf_fast(gr[96 + hh] + bia[64 + hh] + r * (gr[64 + hh] + bia[96 + hh]));
        float hp = hin[(size_t)b * HH + hb0 + hh];
        hout[(size_t)b * HH + hb0 + hh] = n + z * (hp - n);
    }
}

// ---------------- final prediction head ----------------
__global__ __launch_bounds__(288) void pred_kernel(
        const float* __restrict__ Wfc, const float* __restrict__ bfc,
        float* __restrict__ out, int s) {
    int b = blockIdx.x, tid = threadIdx.x;
    const float* h = &g_hd[(s + 1) & 1][(size_t)b * HH];
    __shared__ float hs[HH];
    if (tid < HH) hs[tid] = h[tid];
    __syncthreads();
    int w = tid >> 5, lane = tid & 31;
    float sacc = 0.0f;
#pragma unroll
    for (int i = 0; i < 8; i++) {
        int hh = lane + 32 * i;
        sacc += hs[hh] * Wfc[w * HH + hh];
    }
    sacc = warp_sum(sacc);
    if (lane == 0) {
        out[((size_t)b * PL + s) * OUTD + w] = sacc + bfc[w];
    }
}

// ---------------- host orchestration ----------------
extern "C" void kernel_launch(void* const* d_in, const int* in_sizes, int n_in,
                              void* d_out, int out_size) {
    const float* x    = (const float*)d_in[0];
    const float* Wa   = (const float*)d_in[1];
    const float* ba   = (const float*)d_in[2];
    const float* va   = (const float*)d_in[3];
    const float* eWih = (const float*)d_in[4];
    const float* eWhh = (const float*)d_in[5];
    const float* ebih = (const float*)d_in[6];
    const float* ebhh = (const float*)d_in[7];
    const float* dWih = (const float*)d_in[8];
    const float* dWhh = (const float*)d_in[9];
    const float* dbih = (const float*)d_in[10];
    const float* dbhh = (const float*)d_in[11];
    const float* Wt   = (const float*)d_in[12];
    const float* bt   = (const float*)d_in[13];
    const float* vt   = (const float*)d_in[14];
    const float* Wfc  = (const float*)d_in[15];
    const float* bfc  = (const float*)d_in[16];
    float* out = (float*)d_out;

    init_a_kernel<<<256, 256>>>(x);
    init_w_kernel<<<256, 256>>>(Wt, dWih, dWhh);
    agent_attn_kernel<<<(BB * TT) / 8, 256>>>(x, Wa, ba, va);

    cudaFuncSetAttribute(enc_persistent,
                         cudaFuncAttributeMaxDynamicSharedMemorySize, ENC_SMEM);
    enc_persistent<<<128, 256, ENC_SMEM>>>(eWhh, eWih, ebih, ebhh);

    cudaFuncSetAttribute(eproj_kernel,
                         cudaFuncAttributeMaxDynamicSharedMemorySize, EP_SMEM);
    eproj_kernel<<<dim3((BB * TT) / 64, HH / 64), 256, EP_SMEM>>>();

    cudaFuncSetAttribute(dec_gru_mma,
                         cudaFuncAttributeMaxDynamicSharedMemorySize, GRU_SMEM);
    for (int s = 0; s < PL; s++) {
        dec_attn2_kernel<<<BB, 256>>>(vt, bt, Wfc, bfc, out, s);
        dec_gru_mma<<<dim3(16, 8), 256, GRU_SMEM>>>(dbih, dbhh, s);
    }
    pred_kernel<<<BB, 288>>>(Wfc, bfc, out, PL - 1);
}